// round 14
// baseline (speedup 1.0000x reference)
#include <cuda_runtime.h>
#include <cuda_fp16.h>
#include <cstdint>
#include <cstddef>

// Problem constants
#define BB 2
#define TT 2048
#define DD 768
#define HH 12
#define HS 64
#define FF 3072
#define HALF 1536
#define NT (BB*TT)       // 4096
#define QKVN 2304        // fused q|k|v output width
#define BH 24            // B*H
// 768^-0.5 * log2(e)  (Q pre-scale so scores feed ex2 directly)
#define SCL2 0.05205878339613894f

// ---------------- scratch (device globals) -----------------------------------
__device__ float g_x1 [(size_t)NT*DD];
__device__ __half g_ah [(size_t)NT*DD];    // rmsnorm1 out
__device__ __half g_qh [(size_t)NT*DD];    // Q (pre-scaled), from QKV epilogue
__device__ __half g_atb[(size_t)NT*DD];    // attention out
__device__ __half g_h2b[(size_t)NT*DD];    // rmsnorm2 out
__device__ __half g_swb[(size_t)NT*HALF];  // swiglu out (from W1 epi)
__device__ __half g_kb [(size_t)BH*TT*HS]; // K [bh][t][64]
__device__ __half g_vb [(size_t)BH*TT*HS]; // V^T [bh][hs][T]
// split-K attention partials: [qt-4][bh][part(4)][128][64]  (o fp16, l fp32)
__device__ __half g_po [(size_t)12*24*4*128*64];
__device__ float  g_pl [(size_t)12*24*4*128];
// fp16 weights, layout [N][K]
__device__ __half g_bqkv[(size_t)QKVN*DD];
__device__ __half g_bo  [(size_t)DD*DD];
__device__ __half g_b1  [(size_t)FF*DD];   // column-interleaved (val,gate)
__device__ __half g_b2  [(size_t)DD*HALF];

// ---------------- helpers ----------------------------------------------------
__device__ __forceinline__ uint32_t smem_u32(const void* p) {
    uint32_t a;
    asm("{ .reg .u64 t; cvta.to.shared.u64 t, %1; cvt.u32.u64 %0, t; }" : "=r"(a) : "l"(p));
    return a;
}
__device__ __forceinline__ float ex2f(float x) {
    float r; asm("ex2.approx.ftz.f32 %0, %1;" : "=f"(r) : "f"(x)); return r;
}
#define CPASYNC(d, s) asm volatile("cp.async.cg.shared.global [%0], [%1], 16;" :: "r"(d), "l"(s) : "memory")
#define CPCOMMIT()    asm volatile("cp.async.commit_group;" ::: "memory")
#define CPWAIT(n)     asm volatile("cp.async.wait_group %0;" :: "n"(n) : "memory")
#define LDSM4(r, a)                                                              \
    asm volatile("ldmatrix.sync.aligned.m8n8.x4.shared.b16 {%0,%1,%2,%3}, [%4];" \
        : "=r"((r)[0]), "=r"((r)[1]), "=r"((r)[2]), "=r"((r)[3]) : "r"(a))
#define MMA16816(c, a, b0, b1)                                                   \
    asm volatile("mma.sync.aligned.m16n8k16.row.col.f32.f16.f16.f32 "            \
        "{%0,%1,%2,%3}, {%4,%5,%6,%7}, {%8,%9}, {%0,%1,%2,%3};"                  \
        : "+f"((c)[0]), "+f"((c)[1]), "+f"((c)[2]), "+f"((c)[3])                 \
        : "r"((a)[0]), "r"((a)[1]), "r"((a)[2]), "r"((a)[3]), "r"(b0), "r"(b1))

__device__ __forceinline__ uint32_t packh(__half a, __half b) {
    return (uint32_t)__half_as_ushort(a) | ((uint32_t)__half_as_ushort(b) << 16);
}

// ---------------- coalesced weight prep: smem tile transpose -------------------
__global__ void __launch_bounds__(256) prep_tr(
    const float* __restrict__ Wq, const float* __restrict__ Wk,
    const float* __restrict__ Wv, const float* __restrict__ Wo,
    const float* __restrict__ W1, const float* __restrict__ W2,
    __half* __restrict__ bqkv, __half* __restrict__ bo,
    __half* __restrict__ b1,  __half* __restrict__ b2)
{
    __shared__ float ts[32][33];
    int bid = blockIdx.x;
    int tx = threadIdx.x & 31, ty = threadIdx.x >> 5;

    const float* W; __half* dst;
    int K, mode, srcLd, tn, tk;
    if (bid < 2304) {
        int m = bid / 576, lt = bid - m * 576;
        W = (m == 0) ? Wq : (m == 1) ? Wk : (m == 2) ? Wv : Wo;
        dst = (m < 3) ? bqkv + (size_t)m * 768 * 768 : bo;
        K = 768; mode = (m < 3) ? 1 : 0; srcLd = 768;
        tn = lt / 24; tk = lt - (lt / 24) * 24;
    } else if (bid < 4608) {
        int lt = bid - 2304;
        W = W1; dst = b1; K = 768; mode = 2; srcLd = 3072;
        tn = lt / 24; tk = lt - (lt / 24) * 24;
    } else {
        int lt = bid - 4608;
        W = W2; dst = b2; K = 1536; mode = 0; srcLd = 768;
        tn = lt / 48; tk = lt - (lt / 48) * 48;
    }
    int k0 = tk * 32, n0 = tn * 32;

    #pragma unroll
    for (int i = 0; i < 4; i++) {
        int kk = ty + i * 8;
        float v; int col;
        if (mode == 0) {
            v = W[(size_t)(k0 + kk) * srcLd + n0 + tx];
            col = tx;
        } else if (mode == 1) {
            v = W[(size_t)(n0 >> 6) * (768 * 64) + (size_t)(k0 + kk) * 64 + (n0 & 63) + tx];
            col = tx;
        } else {
            int j = tx & 15, grp = tx >> 4;
            v = W[(size_t)(k0 + kk) * 3072 + (grp ? HALF : 0) + (n0 >> 1) + j];
            col = 2 * j + grp;
        }
        ts[kk][col] = v;
    }
    __syncthreads();
    #pragma unroll
    for (int i = 0; i < 4; i++) {
        int nn = ty + i * 8;
        dst[(size_t)(n0 + nn) * K + k0 + tx] = __float2half_rn(ts[tx][nn]);
    }
}
#define PREP_GRID 5760

// ---------------- mma.sync fp16 GEMM ------------------------------------------
// CTA 128x64, 128 threads (2x2 warps, warp tile 64x32), K-block 64, 4 CTAs/SM.
#define KB 64
#define PADE 72
#define ATILE (128*PADE*2)       // 18432
#define BTILE (64*PADE*2)        // 9216
#define STGB  (ATILE+BTILE)      // 27648
#define GEMM_SMEM (2*STGB)       // 55296

__global__ void __launch_bounds__(128, 4) gemm_mma(
    const __half* __restrict__ Ap, const __half* __restrict__ Bp,
    const float* __restrict__ bias, const float* __restrict__ resid,
    float* __restrict__ C, __half* __restrict__ Csp,
    __half* __restrict__ Kout, __half* __restrict__ Vout,
    int M, int N, int K, int emode)
{
    extern __shared__ char sm[];
    int tid = threadIdx.x, lane = tid & 31, wid = tid >> 5;
    int wm = wid >> 1, wn = wid & 1;
    int bm = blockIdx.y * 128, bn = blockIdx.x * 64;
    uint32_t sbase = smem_u32(sm);

    float acc[4][4][4];
    #pragma unroll
    for (int i = 0; i < 4; i++)
        #pragma unroll
        for (int j = 0; j < 4; j++)
            #pragma unroll
            for (int q = 0; q < 4; q++) acc[i][j][q] = 0.f;

    int a_r = lane & 15, a_c = (lane & 16) ? 8 : 0;
    int b_r = ((lane >> 4) << 3) + (lane & 7), b_c = (lane & 8);
    const int KBn = K / KB;

    auto load_stage = [&](int kb, int stg) {
        #pragma unroll
        for (int i = 0; i < 12; i++) {
            int c = i * 128 + tid;
            int row = c >> 3, cc = c & 7;
            uint32_t dst;
            const __half* src;
            if (i < 8) {
                dst = sbase + stg * STGB + (uint32_t)(row * (PADE * 2) + cc * 16);
                src = Ap + (size_t)(bm + row) * K + kb * KB + cc * 8;
            } else {
                int r2 = row - 128;
                dst = sbase + stg * STGB + ATILE + (uint32_t)(r2 * (PADE * 2) + cc * 16);
                src = Bp + (size_t)(bn + r2) * K + kb * KB + cc * 8;
            }
            CPASYNC(dst, src);
        }
    };

    load_stage(0, 0);
    CPCOMMIT();

    for (int kb = 0; kb < KBn; kb++) {
        CPWAIT(0);
        __syncthreads();
        if (kb + 1 < KBn) { load_stage(kb + 1, (kb + 1) & 1); CPCOMMIT(); }

        uint32_t sa = sbase + (kb & 1) * STGB;
        uint32_t aof = sa, bof = sa + ATILE;
        #pragma unroll
        for (int ks = 0; ks < KB; ks += 16) {
            uint32_t af[4][4], bf2[2][4];
            #pragma unroll
            for (int mt = 0; mt < 4; mt++) {
                uint32_t off = (uint32_t)(((wm * 64 + mt * 16 + a_r) * PADE + ks + a_c) * 2);
                LDSM4(af[mt], aof + off);
            }
            #pragma unroll
            for (int np = 0; np < 2; np++) {
                uint32_t off = (uint32_t)(((wn * 32 + np * 16 + b_r) * PADE + ks + b_c) * 2);
                LDSM4(bf2[np], bof + off);
            }
            #pragma unroll
            for (int mt = 0; mt < 4; mt++)
                #pragma unroll
                for (int nt = 0; nt < 4; nt++)
                    MMA16816(acc[mt][nt], af[mt],
                             bf2[nt >> 1][(nt & 1) * 2], bf2[nt >> 1][(nt & 1) * 2 + 1]);
        }
    }

    int g = lane >> 2, t = lane & 3;
    if (emode == 0) {
        #pragma unroll
        for (int mt = 0; mt < 4; mt++) {
            #pragma unroll
            for (int half = 0; half < 2; half++) {
                int row = bm + wm * 64 + mt * 16 + g + half * 8;
                float* cp = C + (size_t)row * N;
                const float* rp = resid ? (resid + (size_t)row * N) : nullptr;
                #pragma unroll
                for (int nt = 0; nt < 4; nt++) {
                    int col = bn + wn * 32 + nt * 8 + t * 2;
                    float2 v;
                    v.x = acc[mt][nt][half * 2 + 0];
                    v.y = acc[mt][nt][half * 2 + 1];
                    if (bias) {
                        float2 b2v = *(const float2*)(bias + col);
                        v.x += b2v.x; v.y += b2v.y;
                    }
                    if (rp) {
                        float2 r2v = *(const float2*)(rp + col);
                        v.x += r2v.x; v.y += r2v.y;
                    }
                    *(float2*)(cp + col) = v;
                }
            }
        }
    } else if (emode == 1) {
        #pragma unroll
        for (int mt = 0; mt < 4; mt++) {
            #pragma unroll
            for (int half = 0; half < 2; half++) {
                int row = bm + wm * 64 + mt * 16 + g + half * 8;
                #pragma unroll
                for (int nt = 0; nt < 4; nt++) {
                    int gcol = bn + wn * 32 + nt * 8 + t * 2;
                    int j = gcol >> 1;
                    float val = acc[mt][nt][half * 2 + 0] + bias[j];
                    float gt  = acc[mt][nt][half * 2 + 1] + bias[HALF + j];
                    float s = gt / (1.0f + __expf(-gt));
                    Csp[(size_t)row * HALF + j] = __float2half_rn(s * val);
                }
            }
        }
    } else {
        #pragma unroll
        for (int mt = 0; mt < 4; mt++) {
            #pragma unroll
            for (int half = 0; half < 2; half++) {
                int row = bm + wm * 64 + mt * 16 + g + half * 8;
                int bq = row >> 11, t2 = row & (TT - 1);
                #pragma unroll
                for (int nt = 0; nt < 4; nt++) {
                    int col = bn + wn * 32 + nt * 8 + t * 2;
                    float vx = acc[mt][nt][half * 2 + 0];
                    float vy = acc[mt][nt][half * 2 + 1];
                    if (col < DD) {
                        *(uint32_t*)(Csp + (size_t)row * DD + col) =
                            packh(__float2half_rn(vx * SCL2), __float2half_rn(vy * SCL2));
                    } else if (col < 2 * DD) {
                        int c = col - DD; int h2 = c >> 6, hs = c & 63;
                        *(uint32_t*)(Kout + (((size_t)(bq * HH + h2) * TT + t2) << 6) + hs) =
                            packh(__float2half_rn(vx), __float2half_rn(vy));
                    } else {
                        int c = col - 2 * DD; int h2 = c >> 6, hs = c & 63;
                        size_t a0 = ((size_t)(bq * HH + h2) * 64 + hs) * TT + t2;
                        Vout[a0]      = __float2half_rn(vx);
                        Vout[a0 + TT] = __float2half_rn(vy);
                    }
                }
            }
        }
    }
}

// ---------------- tensor-core causal flash attention (fp16, fine split-K) -----
// 40 units per bh (tile spans <= 8), longest-first via blockIdx.y ordering.
// qt<=3 unsplit -> direct output; qt>=4 parts -> fp16 o-partials, fp32 l.
#define ATT_STG 18432
#define ATT_SMEM (18432 + 3*ATT_STG)   // 73728

__global__ void __launch_bounds__(256, 2) attn_tc(
    const __half* __restrict__ Qb, const __half* __restrict__ KBi,
    const __half* __restrict__ VBi, __half* __restrict__ ATB,
    __half* __restrict__ Po, float* __restrict__ Pl)
{
    static const signed char UQT[40] = {15,15,15,15,14,14,11,11,11,10,7,7,3,
                                        14,14,13,13,13,13,12,12,10,10,9,9,6,6,
                                        12,12,9,8,8,8,5,5,2,4,4,1,0};
    static const signed char UPP[40] = {0,1,2,3,0,1,0,1,2,0,0,1,0,
                                        2,3,0,1,2,3,0,1,1,2,0,1,0,1,
                                        2,3,2,0,1,2,0,1,0,0,1,0,0};
    static const signed char UST[40] = {0,8,16,24,0,8,0,8,16,0,0,8,0,
                                        16,23,0,7,14,21,0,7,8,15,0,7,0,7,
                                        14,20,14,0,6,12,0,6,0,0,5,0,0};
    static const signed char ULN[40] = {8,8,8,8,8,8,8,8,8,8,8,8,8,
                                        7,7,7,7,7,7,7,7,7,7,7,7,7,7,
                                        6,6,6,6,6,6,6,6,6,5,5,4,2};
    extern __shared__ char sm[];
    uint32_t sbase = smem_u32(sm);
    int tid = threadIdx.x, lane = tid & 31, wid = tid >> 5;
    int bh = blockIdx.x, u = blockIdx.y;
    int qt = UQT[u], part = UPP[u];
    int kt0 = UST[u], nloc = ULN[u];
    int b = bh / HH, hh = bh % HH;
    int q0 = qt * 128;

    int a_r = lane & 15, a_c = (lane & 16) ? 8 : 0;
    int b_r = ((lane >> 4) << 3) + (lane & 7), b_c = lane & 8;
    int g = lane >> 2, tq = lane & 3;
    const uint32_t ONES = 0x3C003C00u;

    auto ldkv = [&](int kt, int stg) {
        uint32_t sb2 = sbase + 18432 + stg * ATT_STG;
        size_t kbase = ((size_t)bh * TT + kt * 64) * HS;
        size_t vbase = (size_t)bh * HS * TT + kt * 64;
        #pragma unroll
        for (int i = 0; i < 4; i++) {
            int ch = i * 256 + tid;
            int tile = ch >> 9;
            int r = (ch >> 3) & 63, cc = ch & 7;
            uint32_t dst = sb2 + tile * 9216 + r * 144 + cc * 16;
            const __half* src = (tile == 0)
                ? KBi + kbase + r * 64 + cc * 8
                : VBi + vbase + (size_t)r * TT + cc * 8;
            CPASYNC(dst, src);
        }
    };

    #pragma unroll
    for (int i = 0; i < 4; i++) {
        int p = i * 256 + tid;
        int row = p >> 3, cc = p & 7;
        CPASYNC(sbase + (uint32_t)(row * 144 + cc * 16),
                Qb + (size_t)(b * TT + q0 + row) * DD + hh * HS + cc * 8);
    }
    CPCOMMIT();
    ldkv(kt0, 0);     CPCOMMIT();
    ldkv(kt0 + 1, 1); CPCOMMIT();

    float oacc[8][4];
    #pragma unroll
    for (int n = 0; n < 8; n++)
        #pragma unroll
        for (int j = 0; j < 4; j++) oacc[n][j] = 0.f;
    float lacc[4] = {0.f, 0.f, 0.f, 0.f};

    for (int it = 0; it < nloc; it++) {
        if (it + 1 < nloc) { CPWAIT(1); } else { CPWAIT(0); }
        __syncthreads();
        if (it + 2 < nloc) { ldkv(kt0 + it + 2, (it + 2) % 3); CPCOMMIT(); }

        int kt = kt0 + it;
        uint32_t KHb = sbase + 18432 + (it % 3) * ATT_STG;
        uint32_t VHb = KHb + 9216;

        float sacc[8][4];
        #pragma unroll
        for (int n = 0; n < 8; n++)
            #pragma unroll
            for (int j = 0; j < 4; j++) sacc[n][j] = 0.f;

        #pragma unroll
        for (int ks = 0; ks < 4; ks++) {
            uint32_t qh[4];
            uint32_t qa = sbase + (uint32_t)(((wid * 16 + a_r) * 72 + ks * 16 + a_c) * 2);
            LDSM4(qh, qa);
            #pragma unroll
            for (int nt2 = 0; nt2 < 4; nt2++) {
                uint32_t kf[4];
                uint32_t ka = (uint32_t)(((nt2 * 16 + b_r) * 72 + ks * 16 + b_c) * 2);
                LDSM4(kf, KHb + ka);
                MMA16816(sacc[2*nt2],     qh, kf[0], kf[1]);
                MMA16816(sacc[2*nt2 + 1], qh, kf[2], kf[3]);
            }
        }

        if (kt >= 2 * qt) {        // diagonal tiles only
            int r0 = q0 + wid * 16 + g, r1 = r0 + 8;
            int cb = kt * 64 + tq * 2;
            #pragma unroll
            for (int n = 0; n < 8; n++) {
                #pragma unroll
                for (int j = 0; j < 4; j++) {
                    int c = cb + n * 8 + (j & 1);
                    int r = (j < 2) ? r0 : r1;
                    sacc[n][j] = (c <= r) ? ex2f(sacc[n][j]) : 0.f;
                }
            }
        } else {
            #pragma unroll
            for (int n = 0; n < 8; n++)
                #pragma unroll
                for (int j = 0; j < 4; j++)
                    sacc[n][j] = ex2f(sacc[n][j]);
        }

        #pragma unroll
        for (int pk = 0; pk < 4; pk++) {
            uint32_t pa[4];
            pa[0] = packh(__float2half_rn(sacc[2*pk][0]),   __float2half_rn(sacc[2*pk][1]));
            pa[1] = packh(__float2half_rn(sacc[2*pk][2]),   __float2half_rn(sacc[2*pk][3]));
            pa[2] = packh(__float2half_rn(sacc[2*pk+1][0]), __float2half_rn(sacc[2*pk+1][1]));
            pa[3] = packh(__float2half_rn(sacc[2*pk+1][2]), __float2half_rn(sacc[2*pk+1][3]));
            MMA16816(lacc, pa, ONES, ONES);
            #pragma unroll
            for (int nt2 = 0; nt2 < 4; nt2++) {
                uint32_t vf[4];
                uint32_t va = (uint32_t)(((nt2 * 16 + b_r) * 72 + pk * 16 + b_c) * 2);
                LDSM4(vf, VHb + va);
                MMA16816(oacc[2*nt2],     pa, vf[0], vf[1]);
                MMA16816(oacc[2*nt2 + 1], pa, vf[2], vf[3]);
            }
        }
    }

    if (qt <= 3) {
        // unsplit: normalize and write fp16 output directly
        float inv0 = 1.0f / lacc[0], inv1 = 1.0f / lacc[2];
        size_t rg0 = (size_t)(b * TT + q0 + wid * 16 + g);
        size_t rg1 = rg0 + 8;
        int lc = hh * HS + tq * 2;
        #pragma unroll
        for (int n = 0; n < 8; n++) {
            *(uint32_t*)(ATB + rg0 * DD + lc + n * 8) =
                packh(__float2half_rn(oacc[n][0] * inv0), __float2half_rn(oacc[n][1] * inv0));
            *(uint32_t*)(ATB + rg1 * DD + lc + n * 8) =
                packh(__float2half_rn(oacc[n][2] * inv1), __float2half_rn(oacc[n][3] * inv1));
        }
    } else {
        // split part: write fp16 o-partials at [qt-4][bh][part]
        int slot = ((qt - 4) * 24 + bh) * 4 + part;
        int r0 = wid * 16 + g;
        __half* p0 = Po + ((size_t)slot * 128 + r0) * 64 + tq * 2;
        __half* p1 = Po + ((size_t)slot * 128 + r0 + 8) * 64 + tq * 2;
        #pragma unroll
        for (int n = 0; n < 8; n++) {
            *(uint32_t*)(p0 + n * 8) =
                packh(__float2half_rn(oacc[n][0]), __float2half_rn(oacc[n][1]));
            *(uint32_t*)(p1 + n * 8) =
                packh(__float2half_rn(oacc[n][2]), __float2half_rn(oacc[n][3]));
        }
        if (tq == 0) {
            Pl[(size_t)slot * 128 + r0]     = lacc[0];
            Pl[(size_t)slot * 128 + r0 + 8] = lacc[2];
        }
    }
}

// ---------------- merge split-K attention partials -----------------------------
// qt 4..15: sum np = ceil((2qt+2)/8) parts. 12 x 24 x 128 x 32 threads.
__global__ void __launch_bounds__(256) attn_merge(
    const __half* __restrict__ Po, const float* __restrict__ Pl,
    __half* __restrict__ ATB)
{
    int idx = blockIdx.x * 256 + threadIdx.x;
    int cp = idx & 31;
    int t  = idx >> 5;
    int row = t & 127;
    int t2 = t >> 7;
    int bh = t2 % 24, qi = t2 / 24;
    int qt = qi + 4;
    int np = (2 * qt + 2 + 7) >> 3;
    int b = bh / HH, hh = bh % HH;

    size_t slot0 = (size_t)(qi * 24 + bh) * 4;
    float ox = 0.f, oy = 0.f, l = 0.f;
    for (int p = 0; p < np; p++) {
        size_t sp = slot0 + p;
        __half2 v = *(const __half2*)(Po + (sp * 128 + row) * 64 + cp * 2);
        float2 vf = __half22float2(v);
        ox += vf.x; oy += vf.y;
        l += Pl[sp * 128 + row];
    }
    float inv = 1.0f / l;

    size_t gr = (size_t)(b * TT + qt * 128 + row);
    *(uint32_t*)(ATB + gr * DD + hh * HS + cp * 2) =
        packh(__float2half_rn(ox * inv), __float2half_rn(oy * inv));
}

// ---------------- RMSNorm -> fp16 ---------------------------------------------
__global__ void __launch_bounds__(256) rmsnorm_h(
    const float* __restrict__ x, const float* __restrict__ gw,
    __half* __restrict__ o)
{
    int row = blockIdx.x;
    const float* xr = x + (size_t)row * DD;
    int tid = threadIdx.x;
    float ss = 0.f;
    for (int i = tid; i < DD; i += 256) { float v = xr[i]; ss += v * v; }
    #pragma unroll
    for (int o2 = 16; o2 > 0; o2 >>= 1) ss += __shfl_xor_sync(0xffffffffu, ss, o2);
    __shared__ float red[8];
    if ((tid & 31) == 0) red[tid >> 5] = ss;
    __syncthreads();
    if (tid < 8) {
        float v = red[tid];
        #pragma unroll
        for (int o2 = 4; o2 > 0; o2 >>= 1) v += __shfl_xor_sync(0xffu, v, o2);
        if (tid == 0) red[0] = v;
    }
    __syncthreads();
    float rms = sqrtf(red[0] * (1.0f / DD));
    float inv = 1.0f / (rms + 1e-8f);
    for (int i = tid; i < DD; i += 256)
        o[(size_t)row * DD + i] = __float2half_rn(gw[i] * xr[i] * inv);
}

// ---------------- launch -----------------------------------------------------
extern "C" void kernel_launch(void* const* d_in, const int* in_sizes, int n_in,
                              void* d_out, int out_size)
{
    const float* x  = (const float*)d_in[0];
    const float* Wq = (const float*)d_in[1];
    const float* Wk = (const float*)d_in[2];
    const float* Wv = (const float*)d_in[3];
    const float* Wo = (const float*)d_in[4];
    const float* bo = (const float*)d_in[5];
    const float* W1 = (const float*)d_in[6];
    const float* b1 = (const float*)d_in[7];
    const float* W2 = (const float*)d_in[8];
    const float* b2 = (const float*)d_in[9];
    const float* g1 = (const float*)d_in[10];
    const float* g2 = (const float*)d_in[11];
    float* out = (float*)d_out;

    float *x1, *pl;
    __half *po, *ah, *qh, *atb, *h2b, *swb, *kb, *vb, *bqkv, *bo_, *b1_, *b2_;
    cudaGetSymbolAddress((void**)&x1,  g_x1);
    cudaGetSymbolAddress((void**)&po,  g_po);
    cudaGetSymbolAddress((void**)&pl,  g_pl);
    cudaGetSymbolAddress((void**)&ah,  g_ah);
    cudaGetSymbolAddress((void**)&qh,  g_qh);
    cudaGetSymbolAddress((void**)&atb, g_atb);
    cudaGetSymbolAddress((void**)&h2b, g_h2b);
    cudaGetSymbolAddress((void**)&swb, g_swb);
    cudaGetSymbolAddress((void**)&kb,  g_kb);
    cudaGetSymbolAddress((void**)&vb,  g_vb);
    cudaGetSymbolAddress((void**)&bqkv, g_bqkv);
    cudaGetSymbolAddress((void**)&bo_,  g_bo);
    cudaGetSymbolAddress((void**)&b1_,  g_b1);
    cudaGetSymbolAddress((void**)&b2_,  g_b2);

    cudaFuncSetAttribute(gemm_mma, cudaFuncAttributeMaxDynamicSharedMemorySize, GEMM_SMEM);
    cudaFuncSetAttribute(attn_tc,  cudaFuncAttributeMaxDynamicSharedMemorySize, ATT_SMEM);

    // 0) coalesced weight prep (single launch)
    prep_tr<<<PREP_GRID, 256>>>(Wq, Wk, Wv, Wo, W1, W2, bqkv, bo_, b1_, b2_);

    // 1) ah = fp16(rmsnorm(x, g1))
    rmsnorm_h<<<NT, 256>>>(x, g1, ah);

    // 2) qkv GEMM: epilogue scatters Q (scaled by SCL*log2e), K, V^T per-head
    gemm_mma<<<dim3(QKVN / 64, NT / 128), 128, GEMM_SMEM>>>(
        ah, bqkv, nullptr, nullptr, nullptr, qh, kb, vb, NT, QKVN, DD, 2);

    // 3) attention (fine split-K, 40 units/bh, longest-first)
    attn_tc<<<dim3(BH, 40), 256, ATT_SMEM>>>(qh, kb, vb, atb, po, pl);

    // 4) merge split-K partials into atb (qt 4..15)
    attn_merge<<<4608, 256>>>(po, pl, atb);

    // 5) x1 = x + atb @ Wo + bo
    gemm_mma<<<dim3(DD / 64, NT / 128), 128, GEMM_SMEM>>>(
        atb, bo_, bo, x, x1, nullptr, nullptr, nullptr, NT, DD, DD, 0);

    // 6) h2b = fp16(rmsnorm(x1, g2))
    rmsnorm_h<<<NT, 256>>>(x1, g2, h2b);

    // 7) swb = swiglu(h2b @ W1' + b1)  — fused epilogue, interleaved W1
    gemm_mma<<<dim3(FF / 64, NT / 128), 128, GEMM_SMEM>>>(
        h2b, b1_, b1, nullptr, nullptr, swb, nullptr, nullptr, NT, FF, DD, 1);

    // 8) out = x1 + swb @ W2 + b2
    gemm_mma<<<dim3(DD / 64, NT / 128), 128, GEMM_SMEM>>>(
        swb, b2_, b2, x1, out, nullptr, nullptr, nullptr, NT, DD, HALF, 0);
}

// round 16
// speedup vs baseline: 1.0967x; 1.0967x over previous
#include <cuda_runtime.h>
#include <cuda_fp16.h>
#include <cstdint>
#include <cstddef>

// Problem constants
#define BB 2
#define TT 2048
#define DD 768
#define HH 12
#define HS 64
#define FF 3072
#define HALF 1536
#define NT (BB*TT)       // 4096
#define QKVN 2304        // fused q|k|v output width
#define BH 24            // B*H
// 768^-0.5 * log2(e)  (Q pre-scale so scores feed ex2 directly)
#define SCL2 0.05205878339613894f

// ---------------- scratch (device globals) -----------------------------------
__device__ float g_x1 [(size_t)NT*DD];
__device__ __half g_ah [(size_t)NT*DD];    // rmsnorm1 out
__device__ __half g_qh [(size_t)NT*DD];    // Q (pre-scaled), from QKV epilogue
__device__ __half g_atb[(size_t)NT*DD];    // attention out
__device__ __half g_h2b[(size_t)NT*DD];    // rmsnorm2 out
__device__ __half g_swb[(size_t)NT*HALF];  // swiglu out (from W1 epi)
__device__ __half g_kb [(size_t)BH*TT*HS]; // K [bh][t][64]
__device__ __half g_vb [(size_t)BH*TT*HS]; // V^T [bh][hs][T]
// split-K attention partials: [qt-4][bh][part(4)][128][64]
__device__ float g_po [(size_t)12*24*4*128*64];
__device__ float g_pl [(size_t)12*24*4*128];
// fp16 weights, layout [N][K]
__device__ __half g_bqkv[(size_t)QKVN*DD];
__device__ __half g_bo  [(size_t)DD*DD];
__device__ __half g_b1  [(size_t)FF*DD];   // column-interleaved (val,gate)
__device__ __half g_b2  [(size_t)DD*HALF];

// ---------------- helpers ----------------------------------------------------
__device__ __forceinline__ uint32_t smem_u32(const void* p) {
    uint32_t a;
    asm("{ .reg .u64 t; cvta.to.shared.u64 t, %1; cvt.u32.u64 %0, t; }" : "=r"(a) : "l"(p));
    return a;
}
__device__ __forceinline__ float ex2f(float x) {
    float r; asm("ex2.approx.ftz.f32 %0, %1;" : "=f"(r) : "f"(x)); return r;
}
#define CPASYNC(d, s) asm volatile("cp.async.cg.shared.global [%0], [%1], 16;" :: "r"(d), "l"(s) : "memory")
#define CPCOMMIT()    asm volatile("cp.async.commit_group;" ::: "memory")
#define CPWAIT(n)     asm volatile("cp.async.wait_group %0;" :: "n"(n) : "memory")
#define LDSM4(r, a)                                                              \
    asm volatile("ldmatrix.sync.aligned.m8n8.x4.shared.b16 {%0,%1,%2,%3}, [%4];" \
        : "=r"((r)[0]), "=r"((r)[1]), "=r"((r)[2]), "=r"((r)[3]) : "r"(a))
#define MMA16816(c, a, b0, b1)                                                   \
    asm volatile("mma.sync.aligned.m16n8k16.row.col.f32.f16.f16.f32 "            \
        "{%0,%1,%2,%3}, {%4,%5,%6,%7}, {%8,%9}, {%0,%1,%2,%3};"                  \
        : "+f"((c)[0]), "+f"((c)[1]), "+f"((c)[2]), "+f"((c)[3])                 \
        : "r"((a)[0]), "r"((a)[1]), "r"((a)[2]), "r"((a)[3]), "r"(b0), "r"(b1))

__device__ __forceinline__ uint32_t packh(__half a, __half b) {
    return (uint32_t)__half_as_ushort(a) | ((uint32_t)__half_as_ushort(b) << 16);
}

// ---------------- coalesced weight prep: smem tile transpose -------------------
__global__ void __launch_bounds__(256) prep_tr(
    const float* __restrict__ Wq, const float* __restrict__ Wk,
    const float* __restrict__ Wv, const float* __restrict__ Wo,
    const float* __restrict__ W1, const float* __restrict__ W2,
    __half* __restrict__ bqkv, __half* __restrict__ bo,
    __half* __restrict__ b1,  __half* __restrict__ b2)
{
    __shared__ float ts[32][33];
    int bid = blockIdx.x;
    int tx = threadIdx.x & 31, ty = threadIdx.x >> 5;

    const float* W; __half* dst;
    int K, mode, srcLd, tn, tk;
    if (bid < 2304) {
        int m = bid / 576, lt = bid - m * 576;
        W = (m == 0) ? Wq : (m == 1) ? Wk : (m == 2) ? Wv : Wo;
        dst = (m < 3) ? bqkv + (size_t)m * 768 * 768 : bo;
        K = 768; mode = (m < 3) ? 1 : 0; srcLd = 768;
        tn = lt / 24; tk = lt - (lt / 24) * 24;
    } else if (bid < 4608) {
        int lt = bid - 2304;
        W = W1; dst = b1; K = 768; mode = 2; srcLd = 3072;
        tn = lt / 24; tk = lt - (lt / 24) * 24;
    } else {
        int lt = bid - 4608;
        W = W2; dst = b2; K = 1536; mode = 0; srcLd = 768;
        tn = lt / 48; tk = lt - (lt / 48) * 48;
    }
    int k0 = tk * 32, n0 = tn * 32;

    #pragma unroll
    for (int i = 0; i < 4; i++) {
        int kk = ty + i * 8;
        float v; int col;
        if (mode == 0) {
            v = W[(size_t)(k0 + kk) * srcLd + n0 + tx];
            col = tx;
        } else if (mode == 1) {
            v = W[(size_t)(n0 >> 6) * (768 * 64) + (size_t)(k0 + kk) * 64 + (n0 & 63) + tx];
            col = tx;
        } else {
            int j = tx & 15, grp = tx >> 4;
            v = W[(size_t)(k0 + kk) * 3072 + (grp ? HALF : 0) + (n0 >> 1) + j];
            col = 2 * j + grp;
        }
        ts[kk][col] = v;
    }
    __syncthreads();
    #pragma unroll
    for (int i = 0; i < 4; i++) {
        int nn = ty + i * 8;
        dst[(size_t)(n0 + nn) * K + k0 + tx] = __float2half_rn(ts[tx][nn]);
    }
}
#define PREP_GRID 5760

// ---------------- mma.sync fp16 GEMM ------------------------------------------
// CTA 128x64, 128 threads (2x2 warps, warp tile 64x32), K-block 64, 4 CTAs/SM.
#define KB 64
#define PADE 72
#define ATILE (128*PADE*2)       // 18432
#define BTILE (64*PADE*2)        // 9216
#define STGB  (ATILE+BTILE)      // 27648
#define GEMM_SMEM (2*STGB)       // 55296

__global__ void __launch_bounds__(128, 4) gemm_mma(
    const __half* __restrict__ Ap, const __half* __restrict__ Bp,
    const float* __restrict__ bias, const float* __restrict__ resid,
    float* __restrict__ C, __half* __restrict__ Csp,
    __half* __restrict__ Kout, __half* __restrict__ Vout,
    int M, int N, int K, int emode)
{
    extern __shared__ char sm[];
    int tid = threadIdx.x, lane = tid & 31, wid = tid >> 5;
    int wm = wid >> 1, wn = wid & 1;
    int bm = blockIdx.y * 128, bn = blockIdx.x * 64;
    uint32_t sbase = smem_u32(sm);

    float acc[4][4][4];
    #pragma unroll
    for (int i = 0; i < 4; i++)
        #pragma unroll
        for (int j = 0; j < 4; j++)
            #pragma unroll
            for (int q = 0; q < 4; q++) acc[i][j][q] = 0.f;

    int a_r = lane & 15, a_c = (lane & 16) ? 8 : 0;
    int b_r = ((lane >> 4) << 3) + (lane & 7), b_c = (lane & 8);
    const int KBn = K / KB;

    auto load_stage = [&](int kb, int stg) {
        #pragma unroll
        for (int i = 0; i < 12; i++) {
            int c = i * 128 + tid;
            int row = c >> 3, cc = c & 7;
            uint32_t dst;
            const __half* src;
            if (i < 8) {
                dst = sbase + stg * STGB + (uint32_t)(row * (PADE * 2) + cc * 16);
                src = Ap + (size_t)(bm + row) * K + kb * KB + cc * 8;
            } else {
                int r2 = row - 128;
                dst = sbase + stg * STGB + ATILE + (uint32_t)(r2 * (PADE * 2) + cc * 16);
                src = Bp + (size_t)(bn + r2) * K + kb * KB + cc * 8;
            }
            CPASYNC(dst, src);
        }
    };

    load_stage(0, 0);
    CPCOMMIT();

    for (int kb = 0; kb < KBn; kb++) {
        CPWAIT(0);
        __syncthreads();
        if (kb + 1 < KBn) { load_stage(kb + 1, (kb + 1) & 1); CPCOMMIT(); }

        uint32_t sa = sbase + (kb & 1) * STGB;
        uint32_t aof = sa, bof = sa + ATILE;
        #pragma unroll
        for (int ks = 0; ks < KB; ks += 16) {
            uint32_t af[4][4], bf2[2][4];
            #pragma unroll
            for (int mt = 0; mt < 4; mt++) {
                uint32_t off = (uint32_t)(((wm * 64 + mt * 16 + a_r) * PADE + ks + a_c) * 2);
                LDSM4(af[mt], aof + off);
            }
            #pragma unroll
            for (int np = 0; np < 2; np++) {
                uint32_t off = (uint32_t)(((wn * 32 + np * 16 + b_r) * PADE + ks + b_c) * 2);
                LDSM4(bf2[np], bof + off);
            }
            #pragma unroll
            for (int mt = 0; mt < 4; mt++)
                #pragma unroll
                for (int nt = 0; nt < 4; nt++)
                    MMA16816(acc[mt][nt], af[mt],
                             bf2[nt >> 1][(nt & 1) * 2], bf2[nt >> 1][(nt & 1) * 2 + 1]);
        }
    }

    int g = lane >> 2, t = lane & 3;
    if (emode == 0) {
        #pragma unroll
        for (int mt = 0; mt < 4; mt++) {
            #pragma unroll
            for (int half = 0; half < 2; half++) {
                int row = bm + wm * 64 + mt * 16 + g + half * 8;
                float* cp = C + (size_t)row * N;
                const float* rp = resid ? (resid + (size_t)row * N) : nullptr;
                #pragma unroll
                for (int nt = 0; nt < 4; nt++) {
                    int col = bn + wn * 32 + nt * 8 + t * 2;
                    float2 v;
                    v.x = acc[mt][nt][half * 2 + 0];
                    v.y = acc[mt][nt][half * 2 + 1];
                    if (bias) {
                        float2 b2v = *(const float2*)(bias + col);
                        v.x += b2v.x; v.y += b2v.y;
                    }
                    if (rp) {
                        float2 r2v = *(const float2*)(rp + col);
                        v.x += r2v.x; v.y += r2v.y;
                    }
                    *(float2*)(cp + col) = v;
                }
            }
        }
    } else if (emode == 1) {
        #pragma unroll
        for (int mt = 0; mt < 4; mt++) {
            #pragma unroll
            for (int half = 0; half < 2; half++) {
                int row = bm + wm * 64 + mt * 16 + g + half * 8;
                #pragma unroll
                for (int nt = 0; nt < 4; nt++) {
                    int gcol = bn + wn * 32 + nt * 8 + t * 2;
                    int j = gcol >> 1;
                    float val = acc[mt][nt][half * 2 + 0] + bias[j];
                    float gt  = acc[mt][nt][half * 2 + 1] + bias[HALF + j];
                    float s = gt / (1.0f + __expf(-gt));
                    Csp[(size_t)row * HALF + j] = __float2half_rn(s * val);
                }
            }
        }
    } else {
        #pragma unroll
        for (int mt = 0; mt < 4; mt++) {
            #pragma unroll
            for (int half = 0; half < 2; half++) {
                int row = bm + wm * 64 + mt * 16 + g + half * 8;
                int bq = row >> 11, t2 = row & (TT - 1);
                #pragma unroll
                for (int nt = 0; nt < 4; nt++) {
                    int col = bn + wn * 32 + nt * 8 + t * 2;
                    float vx = acc[mt][nt][half * 2 + 0];
                    float vy = acc[mt][nt][half * 2 + 1];
                    if (col < DD) {
                        *(uint32_t*)(Csp + (size_t)row * DD + col) =
                            packh(__float2half_rn(vx * SCL2), __float2half_rn(vy * SCL2));
                    } else if (col < 2 * DD) {
                        int c = col - DD; int h2 = c >> 6, hs = c & 63;
                        *(uint32_t*)(Kout + (((size_t)(bq * HH + h2) * TT + t2) << 6) + hs) =
                            packh(__float2half_rn(vx), __float2half_rn(vy));
                    } else {
                        int c = col - 2 * DD; int h2 = c >> 6, hs = c & 63;
                        size_t a0 = ((size_t)(bq * HH + h2) * 64 + hs) * TT + t2;
                        Vout[a0]      = __float2half_rn(vx);
                        Vout[a0 + TT] = __float2half_rn(vy);
                    }
                }
            }
        }
    }
}

// ---------------- tensor-core causal flash attention (fp16, fine split-K) -----
// 40 units per bh (tile spans <= 8), longest-first via blockIdx.y ordering.
// qt<=3 unsplit -> direct output; qt>=4 parts -> fp32 partials, additive merge.
#define ATT_STG 18432
#define ATT_SMEM (18432 + 3*ATT_STG)   // 73728

__global__ void __launch_bounds__(256, 2) attn_tc(
    const __half* __restrict__ Qb, const __half* __restrict__ KBi,
    const __half* __restrict__ VBi, __half* __restrict__ ATB,
    float* __restrict__ Po, float* __restrict__ Pl)
{
    static const signed char UQT[40] = {15,15,15,15,14,14,11,11,11,10,7,7,3,
                                        14,14,13,13,13,13,12,12,10,10,9,9,6,6,
                                        12,12,9,8,8,8,5,5,2,4,4,1,0};
    static const signed char UPP[40] = {0,1,2,3,0,1,0,1,2,0,0,1,0,
                                        2,3,0,1,2,3,0,1,1,2,0,1,0,1,
                                        2,3,2,0,1,2,0,1,0,0,1,0,0};
    static const signed char UST[40] = {0,8,16,24,0,8,0,8,16,0,0,8,0,
                                        16,23,0,7,14,21,0,7,8,15,0,7,0,7,
                                        14,20,14,0,6,12,0,6,0,0,5,0,0};
    static const signed char ULN[40] = {8,8,8,8,8,8,8,8,8,8,8,8,8,
                                        7,7,7,7,7,7,7,7,7,7,7,7,7,7,
                                        6,6,6,6,6,6,6,6,6,5,5,4,2};
    extern __shared__ char sm[];
    uint32_t sbase = smem_u32(sm);
    int tid = threadIdx.x, lane = tid & 31, wid = tid >> 5;
    int bh = blockIdx.x, u = blockIdx.y;
    int qt = UQT[u], part = UPP[u];
    int kt0 = UST[u], nloc = ULN[u];
    int b = bh / HH, hh = bh % HH;
    int q0 = qt * 128;

    int a_r = lane & 15, a_c = (lane & 16) ? 8 : 0;
    int b_r = ((lane >> 4) << 3) + (lane & 7), b_c = lane & 8;
    int g = lane >> 2, tq = lane & 3;
    const uint32_t ONES = 0x3C003C00u;

    auto ldkv = [&](int kt, int stg) {
        uint32_t sb2 = sbase + 18432 + stg * ATT_STG;
        size_t kbase = ((size_t)bh * TT + kt * 64) * HS;
        size_t vbase = (size_t)bh * HS * TT + kt * 64;
        #pragma unroll
        for (int i = 0; i < 4; i++) {
            int ch = i * 256 + tid;
            int tile = ch >> 9;
            int r = (ch >> 3) & 63, cc = ch & 7;
            uint32_t dst = sb2 + tile * 9216 + r * 144 + cc * 16;
            const __half* src = (tile == 0)
                ? KBi + kbase + r * 64 + cc * 8
                : VBi + vbase + (size_t)r * TT + cc * 8;
            CPASYNC(dst, src);
        }
    };

    #pragma unroll
    for (int i = 0; i < 4; i++) {
        int p = i * 256 + tid;
        int row = p >> 3, cc = p & 7;
        CPASYNC(sbase + (uint32_t)(row * 144 + cc * 16),
                Qb + (size_t)(b * TT + q0 + row) * DD + hh * HS + cc * 8);
    }
    CPCOMMIT();
    ldkv(kt0, 0);     CPCOMMIT();
    ldkv(kt0 + 1, 1); CPCOMMIT();

    float oacc[8][4];
    #pragma unroll
    for (int n = 0; n < 8; n++)
        #pragma unroll
        for (int j = 0; j < 4; j++) oacc[n][j] = 0.f;
    float lacc[4] = {0.f, 0.f, 0.f, 0.f};

    for (int it = 0; it < nloc; it++) {
        if (it + 1 < nloc) { CPWAIT(1); } else { CPWAIT(0); }
        __syncthreads();
        if (it + 2 < nloc) { ldkv(kt0 + it + 2, (it + 2) % 3); CPCOMMIT(); }

        int kt = kt0 + it;
        uint32_t KHb = sbase + 18432 + (it % 3) * ATT_STG;
        uint32_t VHb = KHb + 9216;

        float sacc[8][4];
        #pragma unroll
        for (int n = 0; n < 8; n++)
            #pragma unroll
            for (int j = 0; j < 4; j++) sacc[n][j] = 0.f;

        #pragma unroll
        for (int ks = 0; ks < 4; ks++) {
            uint32_t qh[4];
            uint32_t qa = sbase + (uint32_t)(((wid * 16 + a_r) * 72 + ks * 16 + a_c) * 2);
            LDSM4(qh, qa);
            #pragma unroll
            for (int nt2 = 0; nt2 < 4; nt2++) {
                uint32_t kf[4];
                uint32_t ka = (uint32_t)(((nt2 * 16 + b_r) * 72 + ks * 16 + b_c) * 2);
                LDSM4(kf, KHb + ka);
                MMA16816(sacc[2*nt2],     qh, kf[0], kf[1]);
                MMA16816(sacc[2*nt2 + 1], qh, kf[2], kf[3]);
            }
        }

        if (kt >= 2 * qt) {        // diagonal tiles only
            int r0 = q0 + wid * 16 + g, r1 = r0 + 8;
            int cb = kt * 64 + tq * 2;
            #pragma unroll
            for (int n = 0; n < 8; n++) {
                #pragma unroll
                for (int j = 0; j < 4; j++) {
                    int c = cb + n * 8 + (j & 1);
                    int r = (j < 2) ? r0 : r1;
                    sacc[n][j] = (c <= r) ? ex2f(sacc[n][j]) : 0.f;
                }
            }
        } else {
            #pragma unroll
            for (int n = 0; n < 8; n++)
                #pragma unroll
                for (int j = 0; j < 4; j++)
                    sacc[n][j] = ex2f(sacc[n][j]);
        }

        #pragma unroll
        for (int pk = 0; pk < 4; pk++) {
            uint32_t pa[4];
            pa[0] = packh(__float2half_rn(sacc[2*pk][0]),   __float2half_rn(sacc[2*pk][1]));
            pa[1] = packh(__float2half_rn(sacc[2*pk][2]),   __float2half_rn(sacc[2*pk][3]));
            pa[2] = packh(__float2half_rn(sacc[2*pk+1][0]), __float2half_rn(sacc[2*pk+1][1]));
            pa[3] = packh(__float2half_rn(sacc[2*pk+1][2]), __float2half_rn(sacc[2*pk+1][3]));
            MMA16816(lacc, pa, ONES, ONES);
            #pragma unroll
            for (int nt2 = 0; nt2 < 4; nt2++) {
                uint32_t vf[4];
                uint32_t va = (uint32_t)(((nt2 * 16 + b_r) * 72 + pk * 16 + b_c) * 2);
                LDSM4(vf, VHb + va);
                MMA16816(oacc[2*nt2],     pa, vf[0], vf[1]);
                MMA16816(oacc[2*nt2 + 1], pa, vf[2], vf[3]);
            }
        }
    }

    if (qt <= 3) {
        // unsplit: normalize and write fp16 output directly
        float inv0 = 1.0f / lacc[0], inv1 = 1.0f / lacc[2];
        size_t rg0 = (size_t)(b * TT + q0 + wid * 16 + g);
        size_t rg1 = rg0 + 8;
        int lc = hh * HS + tq * 2;
        #pragma unroll
        for (int n = 0; n < 8; n++) {
            *(uint32_t*)(ATB + rg0 * DD + lc + n * 8) =
                packh(__float2half_rn(oacc[n][0] * inv0), __float2half_rn(oacc[n][1] * inv0));
            *(uint32_t*)(ATB + rg1 * DD + lc + n * 8) =
                packh(__float2half_rn(oacc[n][2] * inv1), __float2half_rn(oacc[n][3] * inv1));
        }
    } else {
        // split part: write raw fp32 partials at [qt-4][bh][part]
        int slot = ((qt - 4) * 24 + bh) * 4 + part;
        int r0 = wid * 16 + g;
        float* p0 = Po + ((size_t)slot * 128 + r0) * 64 + tq * 2;
        float* p1 = Po + ((size_t)slot * 128 + r0 + 8) * 64 + tq * 2;
        #pragma unroll
        for (int n = 0; n < 8; n++) {
            float2 v0; v0.x = oacc[n][0]; v0.y = oacc[n][1];
            float2 v1; v1.x = oacc[n][2]; v1.y = oacc[n][3];
            *(float2*)(p0 + n * 8) = v0;
            *(float2*)(p1 + n * 8) = v1;
        }
        if (tq == 0) {
            Pl[(size_t)slot * 128 + r0]     = lacc[0];
            Pl[(size_t)slot * 128 + r0 + 8] = lacc[2];
        }
    }
}

// ---------------- merge split-K attention partials -----------------------------
// qt 4..15: sum np = ceil((2qt+2)/8) parts. Thread = one float4 column-quad.
// 12 x 24 x 128 x 16 quads = 589824 threads -> 2304 blocks.
__global__ void __launch_bounds__(256) attn_merge(
    const float* __restrict__ Po, const float* __restrict__ Pl,
    __half* __restrict__ ATB)
{
    int idx = blockIdx.x * 256 + threadIdx.x;
    int cq = idx & 15;                 // column quad (4 floats)
    int t  = idx >> 4;
    int row = t & 127;
    int t2 = t >> 7;
    int bh = t2 % 24, qi = t2 / 24;
    int qt = qi + 4;
    int np = (2 * qt + 2 + 7) >> 3;
    int b = bh / HH, hh = bh % HH;

    size_t slot0 = (size_t)(qi * 24 + bh) * 4;
    float o0 = 0.f, o1 = 0.f, o2 = 0.f, o3 = 0.f, l = 0.f;
    for (int p = 0; p < np; p++) {
        size_t sp = slot0 + p;
        float4 v = *(const float4*)(Po + (sp * 128 + row) * 64 + cq * 4);
        o0 += v.x; o1 += v.y; o2 += v.z; o3 += v.w;
        l += Pl[sp * 128 + row];
    }
    float inv = 1.0f / l;

    size_t gr = (size_t)(b * TT + qt * 128 + row);
    uint32_t w0 = packh(__float2half_rn(o0 * inv), __float2half_rn(o1 * inv));
    uint32_t w1 = packh(__float2half_rn(o2 * inv), __float2half_rn(o3 * inv));
    uint2 wv; wv.x = w0; wv.y = w1;
    *(uint2*)(ATB + gr * DD + hh * HS + cq * 4) = wv;
}

// ---------------- RMSNorm -> fp16 ---------------------------------------------
__global__ void __launch_bounds__(256) rmsnorm_h(
    const float* __restrict__ x, const float* __restrict__ gw,
    __half* __restrict__ o)
{
    int row = blockIdx.x;
    const float* xr = x + (size_t)row * DD;
    int tid = threadIdx.x;
    float ss = 0.f;
    for (int i = tid; i < DD; i += 256) { float v = xr[i]; ss += v * v; }
    #pragma unroll
    for (int o2 = 16; o2 > 0; o2 >>= 1) ss += __shfl_xor_sync(0xffffffffu, ss, o2);
    __shared__ float red[8];
    if ((tid & 31) == 0) red[tid >> 5] = ss;
    __syncthreads();
    if (tid < 8) {
        float v = red[tid];
        #pragma unroll
        for (int o2 = 4; o2 > 0; o2 >>= 1) v += __shfl_xor_sync(0xffu, v, o2);
        if (tid == 0) red[0] = v;
    }
    __syncthreads();
    float rms = sqrtf(red[0] * (1.0f / DD));
    float inv = 1.0f / (rms + 1e-8f);
    for (int i = tid; i < DD; i += 256)
        o[(size_t)row * DD + i] = __float2half_rn(gw[i] * xr[i] * inv);
}

// ---------------- launch -----------------------------------------------------
extern "C" void kernel_launch(void* const* d_in, const int* in_sizes, int n_in,
                              void* d_out, int out_size)
{
    const float* x  = (const float*)d_in[0];
    const float* Wq = (const float*)d_in[1];
    const float* Wk = (const float*)d_in[2];
    const float* Wv = (const float*)d_in[3];
    const float* Wo = (const float*)d_in[4];
    const float* bo = (const float*)d_in[5];
    const float* W1 = (const float*)d_in[6];
    const float* b1 = (const float*)d_in[7];
    const float* W2 = (const float*)d_in[8];
    const float* b2 = (const float*)d_in[9];
    const float* g1 = (const float*)d_in[10];
    const float* g2 = (const float*)d_in[11];
    float* out = (float*)d_out;

    float *x1, *po, *pl;
    __half *ah, *qh, *atb, *h2b, *swb, *kb, *vb, *bqkv, *bo_, *b1_, *b2_;
    cudaGetSymbolAddress((void**)&x1,  g_x1);
    cudaGetSymbolAddress((void**)&po,  g_po);
    cudaGetSymbolAddress((void**)&pl,  g_pl);
    cudaGetSymbolAddress((void**)&ah,  g_ah);
    cudaGetSymbolAddress((void**)&qh,  g_qh);
    cudaGetSymbolAddress((void**)&atb, g_atb);
    cudaGetSymbolAddress((void**)&h2b, g_h2b);
    cudaGetSymbolAddress((void**)&swb, g_swb);
    cudaGetSymbolAddress((void**)&kb,  g_kb);
    cudaGetSymbolAddress((void**)&vb,  g_vb);
    cudaGetSymbolAddress((void**)&bqkv, g_bqkv);
    cudaGetSymbolAddress((void**)&bo_,  g_bo);
    cudaGetSymbolAddress((void**)&b1_,  g_b1);
    cudaGetSymbolAddress((void**)&b2_,  g_b2);

    cudaFuncSetAttribute(gemm_mma, cudaFuncAttributeMaxDynamicSharedMemorySize, GEMM_SMEM);
    cudaFuncSetAttribute(attn_tc,  cudaFuncAttributeMaxDynamicSharedMemorySize, ATT_SMEM);

    // 0) coalesced weight prep (single launch)
    prep_tr<<<PREP_GRID, 256>>>(Wq, Wk, Wv, Wo, W1, W2, bqkv, bo_, b1_, b2_);

    // 1) ah = fp16(rmsnorm(x, g1))
    rmsnorm_h<<<NT, 256>>>(x, g1, ah);

    // 2) qkv GEMM: epilogue scatters Q (scaled by SCL*log2e), K, V^T per-head
    gemm_mma<<<dim3(QKVN / 64, NT / 128), 128, GEMM_SMEM>>>(
        ah, bqkv, nullptr, nullptr, nullptr, qh, kb, vb, NT, QKVN, DD, 2);

    // 3) attention (fine split-K, 40 units/bh, longest-first)
    attn_tc<<<dim3(BH, 40), 256, ATT_SMEM>>>(qh, kb, vb, atb, po, pl);

    // 4) merge split-K partials into atb (qt 4..15)
    attn_merge<<<2304, 256>>>(po, pl, atb);

    // 5) x1 = x + atb @ Wo + bo
    gemm_mma<<<dim3(DD / 64, NT / 128), 128, GEMM_SMEM>>>(
        atb, bo_, bo, x, x1, nullptr, nullptr, nullptr, NT, DD, DD, 0);

    // 6) h2b = fp16(rmsnorm(x1, g2))
    rmsnorm_h<<<NT, 256>>>(x1, g2, h2b);

    // 7) swb = swiglu(h2b @ W1' + b1)  — fused epilogue, interleaved W1
    gemm_mma<<<dim3(FF / 64, NT / 128), 128, GEMM_SMEM>>>(
        h2b, b1_, b1, nullptr, nullptr, swb, nullptr, nullptr, NT, FF, DD, 1);

    // 8) out = x1 + swb @ W2 + b2
    gemm_mma<<<dim3(DD / 64, NT / 128), 128, GEMM_SMEM>>>(
        swb, b2_, b2, x1, out, nullptr, nullptr, nullptr, NT, DD, HALF, 0);
}